// round 7
// baseline (speedup 1.0000x reference)
#include <cuda_runtime.h>
#include <cuda_bf16.h>
#include <cstdint>
#include <math.h>

// Problem constants
#define BATCH  4
#define SEQ    2048
#define DMODEL 512
#define NHEADS 8
#define DHEAD  64
#define DFF    2048
#define NBLOCKS 6
#define NROWS  (BATCH * SEQ)   // 8192

// ---------------------------------------------------------------------------
// Scratch (device globals)
// fp32 activations (residual stream) + packed bf16 hi/lo pair arrays.
// Pair arrays pack 2 consecutive K-elements into one u32 (bf16x2).
// ---------------------------------------------------------------------------
__device__ float    g_h  [NROWS * DMODEL];
__device__ float    g_y  [NROWS * DMODEL];
__device__ float    g_a  [NROWS * DMODEL];
__device__ uint32_t g_hhi [NROWS * 256],  g_hlo [NROWS * 256];
__device__ uint32_t g_yhi [NROWS * 256],  g_ylo [NROWS * 256];
__device__ uint32_t g_aohi[NROWS * 256],  g_aolo[NROWS * 256];
__device__ uint32_t g_midhi[NROWS * 1024], g_midlo[NROWS * 1024];
__device__ uint32_t g_qhi[BATCH*NHEADS*SEQ*32], g_qlo[BATCH*NHEADS*SEQ*32];
__device__ uint32_t g_khi[BATCH*NHEADS*SEQ*32], g_klo[BATCH*NHEADS*SEQ*32];
__device__ __nv_bfloat16 g_vhi[BATCH*NHEADS*DHEAD*SEQ], g_vlo[BATCH*NHEADS*DHEAD*SEQ];
// weights, pre-transposed [N][K/2] packed hi/lo
__device__ uint32_t g_wqkv_hi[NBLOCKS*1536*256], g_wqkv_lo[NBLOCKS*1536*256];
__device__ uint32_t g_w0_hi [NBLOCKS*512*256],  g_w0_lo [NBLOCKS*512*256];
__device__ uint32_t g_l1_hi [NBLOCKS*2048*256], g_l1_lo [NBLOCKS*2048*256];
__device__ uint32_t g_l2_hi [NBLOCKS*512*1024], g_l2_lo [NBLOCKS*512*1024];

__device__ __forceinline__ float gelu_exact(float x) {
    return 0.5f * x * (1.0f + erff(x * 0.70710678118654752f));
}

__device__ __forceinline__ void split2(float x, float y, uint32_t& hi, uint32_t& lo) {
    __nv_bfloat16 hx = __float2bfloat16_rn(x);
    __nv_bfloat16 hy = __float2bfloat16_rn(y);
    float rx = x - __bfloat162float(hx);
    float ry = y - __bfloat162float(hy);
    __nv_bfloat162 H; H.x = hx; H.y = hy;
    __nv_bfloat162 L = __floats2bfloat162_rn(rx, ry);
    hi = *reinterpret_cast<uint32_t*>(&H);
    lo = *reinterpret_cast<uint32_t*>(&L);
}

__device__ __forceinline__ void mma_bf16(float* c, const uint32_t* a, const uint32_t* b) {
    asm volatile(
        "mma.sync.aligned.m16n8k16.row.col.f32.bf16.bf16.f32 "
        "{%0,%1,%2,%3}, {%4,%5,%6,%7}, {%8,%9}, {%0,%1,%2,%3};"
        : "+f"(c[0]), "+f"(c[1]), "+f"(c[2]), "+f"(c[3])
        : "r"(a[0]), "r"(a[1]), "r"(a[2]), "r"(a[3]), "r"(b[0]), "r"(b[1]));
}

__device__ __forceinline__ uint32_t smem_u32(const void* p) {
    uint32_t a;
    asm("{ .reg .u64 t; cvta.to.shared.u64 t, %1; cvt.u32.u64 %0, t; }"
        : "=r"(a) : "l"(p));
    return a;
}
__device__ __forceinline__ void cp16(uint32_t sa, const void* ga) {
    asm volatile("cp.async.ca.shared.global [%0], [%1], 16;" :: "r"(sa), "l"(ga));
}
#define CP_COMMIT() asm volatile("cp.async.commit_group;" ::: "memory")
#define CP_WAIT1()  asm volatile("cp.async.wait_group 1;" ::: "memory")

// ---------------------------------------------------------------------------
// Embedding + PE -> fp32 + hi/lo
// ---------------------------------------------------------------------------
__global__ void embed_k(const int* __restrict__ x, const float* __restrict__ E,
                        const float* __restrict__ pe, float* __restrict__ H,
                        uint32_t* __restrict__ Hhi, uint32_t* __restrict__ Hlo) {
    int idx = blockIdx.x * blockDim.x + threadIdx.x;
    int row = idx >> 7;
    int c   = (idx & 127) << 2;
    int t   = row & (SEQ - 1);
    int tok = x[row];
    float4 e = *(const float4*)(E  + (size_t)tok * DMODEL + c);
    float4 p = *(const float4*)(pe + (size_t)t   * DMODEL + c);
    float4 o = make_float4(e.x + p.x, e.y + p.y, e.z + p.z, e.w + p.w);
    *(float4*)(H + (size_t)row * DMODEL + c) = o;
    uint32_t h0, l0, h1, l1;
    split2(o.x, o.y, h0, l0);
    split2(o.z, o.w, h1, l1);
    size_t pi = (size_t)row * 256 + (c >> 1);
    *(uint2*)(Hhi + pi) = make_uint2(h0, h1);
    *(uint2*)(Hlo + pi) = make_uint2(l0, l1);
}

// ---------------------------------------------------------------------------
// Weight transpose + split:  W[K][N] -> Whi/Wlo [N][K/2]
// ---------------------------------------------------------------------------
__global__ void wtrans_k(const float* __restrict__ W, uint32_t* __restrict__ Whi,
                         uint32_t* __restrict__ Wlo, int K, int N) {
    __shared__ float t[32][33];
    int n0 = blockIdx.x * 32, k0 = blockIdx.y * 32;
    const float* Wz = W + (size_t)blockIdx.z * K * N;
    uint32_t* Whiz = Whi + (size_t)blockIdx.z * N * (K >> 1);
    uint32_t* Wloz = Wlo + (size_t)blockIdx.z * N * (K >> 1);
    int tx = threadIdx.x, ty = threadIdx.y;     // 32 x 8
    int tid = ty * 32 + tx;
#pragma unroll
    for (int i = 0; i < 32; i += 8)
        t[ty + i][tx] = Wz[(size_t)(k0 + ty + i) * N + n0 + tx];
    __syncthreads();
    int kp = tid & 15, nn = tid >> 4;
#pragma unroll
    for (int j = 0; j < 2; j++) {
        int n = nn + 16 * j;
        uint32_t hi, lo;
        split2(t[2 * kp][n], t[2 * kp + 1][n], hi, lo);
        size_t oi = (size_t)(n0 + n) * (K >> 1) + (k0 >> 1) + kp;
        Whiz[oi] = hi;
        Wloz[oi] = lo;
    }
}

// QKV: permuted n' = kv*512 + h*64 + d (orig col n = d*24 + kv*8 + h),
// Q columns (kv==0) pre-scaled by 0.125*log2(e).
__global__ void wqkvtrans_k(const float* __restrict__ W,
                            uint32_t* __restrict__ Whi, uint32_t* __restrict__ Wlo) {
    int z   = blockIdx.y;
    int idx = blockIdx.x * 256 + threadIdx.x;    // over 1536*256
    int k2  = idx & 255;
    int np  = idx >> 8;
    int kv  = np >> 9, h = (np >> 6) & 7, d = np & 63;
    int n   = d * 24 + kv * 8 + h;
    const float* Wz = W + (size_t)z * 512 * 1536;
    float x0 = Wz[(size_t)(2 * k2) * 1536 + n];
    float x1 = Wz[(size_t)(2 * k2 + 1) * 1536 + n];
    if (kv == 0) { x0 *= 0.18033688011112042f; x1 *= 0.18033688011112042f; }
    uint32_t hi, lo;
    split2(x0, x1, hi, lo);
    Whi[(size_t)z * 1536 * 256 + idx] = hi;
    Wlo[(size_t)z * 1536 * 256 + idx] = lo;
}

// ---------------------------------------------------------------------------
// bf16x3 warp-MMA GEMM, pre-split inputs, cp.async 3-stage pipeline.
// CTA 128x128, 8 warps (64x32), K-chunk 32 (16 u32 pairs), 1 sync/chunk.
// Stage (u32): Ahi[128*20] Alo Bhi Blo (10240 u32 = 40KB), 3 stages.
// EPI: 0 plain->C, 1 +bias->C, 2 +bias+gelu->O1 hi/lo, 3 QKV scatter
// ---------------------------------------------------------------------------
#define GSTAGE 10240
#define GMM_SMEM (3 * GSTAGE * 4)

template <int EPI>
__global__ void __launch_bounds__(256) gemm_mma(
    const uint32_t* __restrict__ Ahi, const uint32_t* __restrict__ Alo,
    const uint32_t* __restrict__ Bhi, const uint32_t* __restrict__ Blo,
    const float* __restrict__ bias, float* __restrict__ C,
    uint32_t* __restrict__ O1h, uint32_t* __restrict__ O1l,
    uint32_t* __restrict__ O2h, uint32_t* __restrict__ O2l,
    __nv_bfloat16* __restrict__ O3h, __nv_bfloat16* __restrict__ O3l,
    int M, int N, int K)
{
    extern __shared__ uint32_t sm[];

    const int tid  = threadIdx.x;
    const int wid  = tid >> 5;
    const int lane = tid & 31;
    const int g    = lane >> 2;
    const int cq   = lane & 3;
    const int wm   = (wid & 1) * 64;
    const int wn   = (wid >> 1) * 32;
    const int m0   = blockIdx.y * 128;
    const int n0   = blockIdx.x * 128;
    const int K2   = K >> 1;
    const int NC   = K >> 5;
    const uint32_t sbase = smem_u32(sm);
    const int pu = tid & 3;              // 16B unit within row
    const int pr = tid >> 2;             // base row (0..63)

    // per-chunk cp.async issue: 8 x 16B per thread
    auto issue = [&](int cc) {
        const int k2 = cc << 4;
        const uint32_t sb = sbase + (uint32_t)(cc % 3) * (GSTAGE * 4);
#pragma unroll
        for (int i = 0; i < 8; i++) {
            int r = (64 * i + pr) & 127;
            const uint32_t* gp;
            if (i < 2)      gp = Ahi + (size_t)(m0 + r) * K2;
            else if (i < 4) gp = Alo + (size_t)(m0 + r) * K2;
            else if (i < 6) gp = Bhi + (size_t)(n0 + r) * K2;
            else            gp = Blo + (size_t)(n0 + r) * K2;
            int tile = i >> 1;
            cp16(sb + (uint32_t)(tile * 2560 + r * 20 + pu * 4) * 4, gp + k2 + pu * 4);
        }
    };

    float acc[4][4][4];
#pragma unroll
    for (int mt = 0; mt < 4; mt++)
#pragma unroll
        for (int nt = 0; nt < 4; nt++)
#pragma unroll
            for (int e = 0; e < 4; e++) acc[mt][nt][e] = 0.0f;

    issue(0); CP_COMMIT();
    if (NC > 1) issue(1);
    CP_COMMIT();

    for (int c = 0; c < NC; c++) {
        CP_WAIT1();
        __syncthreads();
        const uint32_t* sp = sm + (c % 3) * GSTAGE;

#pragma unroll
        for (int ks = 0; ks < 2; ks++) {
            const int kb = ks * 8;
            uint32_t bh[4][2], bl[4][2];
#pragma unroll
            for (int nt = 0; nt < 4; nt++) {
                int bi = 5120 + (wn + nt * 8 + g) * 20 + kb + cq;
                bh[nt][0] = sp[bi];
                bh[nt][1] = sp[bi + 4];
                bl[nt][0] = sp[bi + 2560];
                bl[nt][1] = sp[bi + 2560 + 4];
            }
#pragma unroll
            for (int mt = 0; mt < 4; mt++) {
                int ai = (wm + mt * 16 + g) * 20 + kb + cq;
                uint32_t ah[4], al[4];
                ah[0] = sp[ai];             ah[1] = sp[ai + 160];
                ah[2] = sp[ai + 4];         ah[3] = sp[ai + 160 + 4];
                al[0] = sp[ai + 2560];      al[1] = sp[ai + 2560 + 160];
                al[2] = sp[ai + 2560 + 4];  al[3] = sp[ai + 2560 + 160 + 4];
#pragma unroll
                for (int nt = 0; nt < 4; nt++) mma_bf16(acc[mt][nt], ah, bh[nt]);
#pragma unroll
                for (int nt = 0; nt < 4; nt++) mma_bf16(acc[mt][nt], al, bh[nt]);
#pragma unroll
                for (int nt = 0; nt < 4; nt++) mma_bf16(acc[mt][nt], ah, bl[nt]);
            }
        }

        if (c + 2 < NC) issue(c + 2);
        CP_COMMIT();
    }

    // ---- epilogue ----
#pragma unroll
    for (int mt = 0; mt < 4; mt++) {
#pragma unroll
        for (int nt = 0; nt < 4; nt++) {
            int col = n0 + wn + nt * 8 + 2 * cq;
            int r0  = m0 + wm + mt * 16 + g;
            float2 v0 = make_float2(acc[mt][nt][0], acc[mt][nt][1]);
            float2 v1 = make_float2(acc[mt][nt][2], acc[mt][nt][3]);
            if (EPI == 3) {
                int kv = col >> 9, h = (col >> 6) & 7, d = col & 63;
                int b0i = r0 >> 11, t0i = r0 & (SEQ - 1);
                int r1 = r0 + 8;
                int t1i = r1 & (SEQ - 1);
                if (kv == 2) {
                    size_t base0 = (((size_t)b0i * NHEADS + h) * DHEAD + d) * SEQ;
                    __nv_bfloat16 h00 = __float2bfloat16_rn(v0.x);
                    __nv_bfloat16 h01 = __float2bfloat16_rn(v0.y);
                    __nv_bfloat16 h10 = __float2bfloat16_rn(v1.x);
                    __nv_bfloat16 h11 = __float2bfloat16_rn(v1.y);
                    O3h[base0 + t0i]       = h00;
                    O3h[base0 + SEQ + t0i] = h01;
                    O3h[base0 + t1i]       = h10;
                    O3h[base0 + SEQ + t1i] = h11;
                    O3l[base0 + t0i]       = __float2bfloat16_rn(v0.x - __bfloat162float(h00));
                    O3l[base0 + SEQ + t0i] = __float2bfloat16_rn(v0.y - __bfloat162float(h01));
                    O3l[base0 + t1i]       = __float2bfloat16_rn(v1.x - __bfloat162float(h10));
                    O3l[base0 + SEQ + t1i] = __float2bfloat16_rn(v1.y - __bfloat162float(h11));
                } else {
                    uint32_t* dh = (kv == 0) ? O1h : O2h;
                    uint32_t* dl = (kv == 0) ? O1l : O2l;
                    uint32_t hi0, lo0, hi1, lo1;
                    split2(v0.x, v0.y, hi0, lo0);
                    split2(v1.x, v1.y, hi1, lo1);
                    size_t qi0 = (((size_t)b0i * NHEADS + h) * SEQ + t0i) * 32 + (d >> 1);
                    size_t qi1 = (((size_t)b0i * NHEADS + h) * SEQ + t1i) * 32 + (d >> 1);
                    dh[qi0] = hi0; dl[qi0] = lo0;
                    dh[qi1] = hi1; dl[qi1] = lo1;
                }
            } else if (EPI == 2) {
                float2 bb = *(const float2*)(bias + col);
                v0.x = gelu_exact(v0.x + bb.x); v0.y = gelu_exact(v0.y + bb.y);
                v1.x = gelu_exact(v1.x + bb.x); v1.y = gelu_exact(v1.y + bb.y);
                uint32_t hi0, lo0, hi1, lo1;
                split2(v0.x, v0.y, hi0, lo0);
                split2(v1.x, v1.y, hi1, lo1);
                size_t oi0 = (size_t)r0 * (N >> 1) + (col >> 1);
                size_t oi1 = (size_t)(r0 + 8) * (N >> 1) + (col >> 1);
                O1h[oi0] = hi0; O1l[oi0] = lo0;
                O1h[oi1] = hi1; O1l[oi1] = lo1;
            } else {
                if (EPI == 1) {
                    float2 bb = *(const float2*)(bias + col);
                    v0.x += bb.x; v0.y += bb.y;
                    v1.x += bb.x; v1.y += bb.y;
                }
                *(float2*)(C + (size_t)r0 * N + col)       = v0;
                *(float2*)(C + (size_t)(r0 + 8) * N + col) = v1;
            }
        }
    }
}

// ---------------------------------------------------------------------------
// Flash attention, bf16x3 mma.sync, pre-split Q/K/V inputs.
// CTA = 128 queries x 64-key blocks, 8 warps. Smem stride 36 u32.
// Output: pre-split hi/lo (feeds W0 GEMM).
// ---------------------------------------------------------------------------
#define FSC 36
#define FQH 0
#define FQL 4608
#define FKH 9216
#define FKL 11520
#define FVH 13824
#define FVL 16128
#define FLASH2_SMEM (18432 * 4)

__global__ void __launch_bounds__(256, 2) flash_mma(
    const uint32_t* __restrict__ Qhi, const uint32_t* __restrict__ Qlo,
    const uint32_t* __restrict__ Khi, const uint32_t* __restrict__ Klo,
    const __nv_bfloat16* __restrict__ Vhi, const __nv_bfloat16* __restrict__ Vlo,
    uint32_t* __restrict__ Ohi, uint32_t* __restrict__ Olo)
{
    extern __shared__ uint32_t sm[];
    const int tid  = threadIdx.x;
    const int wid  = tid >> 5;
    const int lane = tid & 31;
    const int g    = lane >> 2;
    const int cq   = lane & 3;
    const int t0   = blockIdx.x * 128;
    const int h    = blockIdx.y;
    const int b    = blockIdx.z;
    const size_t bh = ((size_t)b * NHEADS + h) * SEQ;

    // ---- load Q (already prescaled + split) ----
    {
        int row = tid >> 1;
        const uint2* qh = (const uint2*)(Qhi + (bh + t0 + row) * 32);
        const uint2* ql = (const uint2*)(Qlo + (bh + t0 + row) * 32);
#pragma unroll
        for (int i = 0; i < 8; i++) {
            int f4 = (tid & 1) + 2 * i;
            uint2 a = qh[f4], bq = ql[f4];
            int di = row * FSC + f4 * 2;
            sm[FQH + di] = a.x;  sm[FQH + di + 1] = a.y;
            sm[FQL + di] = bq.x; sm[FQL + di + 1] = bq.y;
        }
    }

    float o[8][4];
#pragma unroll
    for (int dt = 0; dt < 8; dt++)
#pragma unroll
        for (int e = 0; e < 4; e++) o[dt][e] = 0.0f;
    float m0 = -1e30f, m1 = -1e30f, l0 = 0.0f, l1 = 0.0f;

    const int prow = tid >> 2;
    const __nv_bfloat16* vhrow = Vhi + ((((size_t)b * NHEADS + h) * DHEAD) + prow) * SEQ;
    const __nv_bfloat16* vlrow = Vlo + ((((size_t)b * NHEADS + h) * DHEAD) + prow) * SEQ;
    const int qr = wid * 16 + g;

    for (int jb = 0; jb < SEQ; jb += 64) {
        __syncthreads();
        const uint2* kh2 = (const uint2*)(Khi + (bh + jb + prow) * 32);
        const uint2* kl2 = (const uint2*)(Klo + (bh + jb + prow) * 32);
        const uint2* vh2 = (const uint2*)(vhrow + jb);
        const uint2* vl2 = (const uint2*)(vlrow + jb);
#pragma unroll
        for (int i = 0; i < 4; i++) {
            int f4 = (tid & 3) + i * 4;
            int di = prow * FSC + f4 * 2;
            uint2 a = kh2[f4], c2 = kl2[f4];
            sm[FKH + di] = a.x;  sm[FKH + di + 1] = a.y;
            sm[FKL + di] = c2.x; sm[FKL + di + 1] = c2.y;
            uint2 w = vh2[f4], z2 = vl2[f4];
            sm[FVH + di] = w.x;  sm[FVH + di + 1] = w.y;
            sm[FVL + di] = z2.x; sm[FVL + di + 1] = z2.y;
        }
        __syncthreads();

        // ---- S = Q @ K^T ----
        float s[8][4];
#pragma unroll
        for (int nt = 0; nt < 8; nt++)
#pragma unroll
            for (int e = 0; e < 4; e++) s[nt][e] = 0.0f;

#pragma unroll
        for (int ks = 0; ks < 4; ks++) {
            uint32_t qh[4], ql[4];
            int qi = qr * FSC + ks * 8 + cq;
            qh[0] = sm[FQH + qi];            qh[1] = sm[FQH + qi + 8 * FSC];
            qh[2] = sm[FQH + qi + 4];        qh[3] = sm[FQH + qi + 8 * FSC + 4];
            ql[0] = sm[FQL + qi];            ql[1] = sm[FQL + qi + 8 * FSC];
            ql[2] = sm[FQL + qi + 4];        ql[3] = sm[FQL + qi + 8 * FSC + 4];
            uint32_t kh[8][2], kl[8][2];
#pragma unroll
            for (int nt = 0; nt < 8; nt++) {
                int ki = (nt * 8 + g) * FSC + ks * 8 + cq;
                kh[nt][0] = sm[FKH + ki]; kh[nt][1] = sm[FKH + ki + 4];
                kl[nt][0] = sm[FKL + ki]; kl[nt][1] = sm[FKL + ki + 4];
            }
#pragma unroll
            for (int nt = 0; nt < 8; nt++) mma_bf16(s[nt], qh, kh[nt]);
#pragma unroll
            for (int nt = 0; nt < 8; nt++) mma_bf16(s[nt], ql, kh[nt]);
#pragma unroll
            for (int nt = 0; nt < 8; nt++) mma_bf16(s[nt], qh, kl[nt]);
        }

        // ---- online softmax (base 2) ----
        float rm0 = -1e30f, rm1 = -1e30f;
#pragma unroll
        for (int nt = 0; nt < 8; nt++) {
            rm0 = fmaxf(rm0, fmaxf(s[nt][0], s[nt][1]));
            rm1 = fmaxf(rm1, fmaxf(s[nt][2], s[nt][3]));
        }
        rm0 = fmaxf(rm0, __shfl_xor_sync(0xffffffffu, rm0, 1));
        rm0 = fmaxf(rm0, __shfl_xor_sync(0xffffffffu, rm0, 2));
        rm1 = fmaxf(rm1, __shfl_xor_sync(0xffffffffu, rm1, 1));
        rm1 = fmaxf(rm1, __shfl_xor_sync(0xffffffffu, rm1, 2));
        float mn0 = fmaxf(m0, rm0), mn1 = fmaxf(m1, rm1);
        float c0 = exp2f(m0 - mn0), c1 = exp2f(m1 - mn1);
        m0 = mn0; m1 = mn1;
        float rs0 = 0.0f, rs1 = 0.0f;
#pragma unroll
        for (int nt = 0; nt < 8; nt++) {
            s[nt][0] = exp2f(s[nt][0] - mn0);
            s[nt][1] = exp2f(s[nt][1] - mn0);
            s[nt][2] = exp2f(s[nt][2] - mn1);
            s[nt][3] = exp2f(s[nt][3] - mn1);
            rs0 += s[nt][0] + s[nt][1];
            rs1 += s[nt][2] + s[nt][3];
        }
        rs0 += __shfl_xor_sync(0xffffffffu, rs0, 1);
        rs0 += __shfl_xor_sync(0xffffffffu, rs0, 2);
        rs1 += __shfl_xor_sync(0xffffffffu, rs1, 1);
        rs1 += __shfl_xor_sync(0xffffffffu, rs1, 2);
        l0 = l0 * c0 + rs0;
        l1 = l1 * c1 + rs1;
#pragma unroll
        for (int dt = 0; dt < 8; dt++) {
            o[dt][0] *= c0; o[dt][1] *= c0;
            o[dt][2] *= c1; o[dt][3] *= c1;
        }

        // ---- P fragments (register-only) ----
        uint32_t ph[4][4], pl[4][4];
#pragma unroll
        for (int kj = 0; kj < 4; kj++) {
            split2(s[2*kj][0],   s[2*kj][1],   ph[kj][0], pl[kj][0]);
            split2(s[2*kj][2],   s[2*kj][3],   ph[kj][1], pl[kj][1]);
            split2(s[2*kj+1][0], s[2*kj+1][1], ph[kj][2], pl[kj][2]);
            split2(s[2*kj+1][2], s[2*kj+1][3], ph[kj][3], pl[kj][3]);
        }

        // ---- O += P @ V ----
#pragma unroll
        for (int kj = 0; kj < 4; kj++) {
            uint32_t vh[8][2], vl[8][2];
#pragma unroll
            for (int dt = 0; dt < 8; dt++) {
                int vi = (dt * 8 + g) * FSC + kj * 8 + cq;
                vh[dt][0] = sm[FVH + vi]; vh[dt][1] = sm[FVH + vi + 4];
                vl[dt][0] = sm[FVL + vi]; vl[dt][1] = sm[FVL + vi + 4];
            }
#pragma unroll
            for (int dt = 0; dt < 8; dt++) mma_bf16(o[dt], ph[kj], vh[dt]);
#pragma unroll
            for (int dt = 0; dt < 8; dt++) mma_bf16(o[dt], pl[kj], vh[dt]);
#pragma unroll
            for (int dt = 0; dt < 8; dt++) mma_bf16(o[dt], ph[kj], vl[dt]);
        }
    }

    // ---- write O (pre-split for next GEMM) ----
    float inv0 = 1.0f / l0, inv1 = 1.0f / l1;
    int row0 = t0 + wid * 16 + g;
#pragma unroll
    for (int dt = 0; dt < 8; dt++) {
        int col = h * DHEAD + dt * 8 + 2 * cq;
        uint32_t hi, lo;
        split2(o[dt][0] * inv0, o[dt][1] * inv0, hi, lo);
        size_t oi0 = ((size_t)b * SEQ + row0) * 256 + (col >> 1);
        Ohi[oi0] = hi; Olo[oi0] = lo;
        split2(o[dt][2] * inv1, o[dt][3] * inv1, hi, lo);
        size_t oi1 = ((size_t)b * SEQ + row0 + 8) * 256 + (col >> 1);
        Ohi[oi1] = hi; Olo[oi1] = lo;
    }
}

// ---------------------------------------------------------------------------
// out = LayerNorm(a + resid) -> fp32 + hi/lo
// ---------------------------------------------------------------------------
__global__ void __launch_bounds__(128) add_ln_k(
    const float* __restrict__ A, const float* __restrict__ R,
    const float* __restrict__ g, const float* __restrict__ bb,
    float* __restrict__ out, uint32_t* __restrict__ Ohi, uint32_t* __restrict__ Olo)
{
    __shared__ float red[4];
    int row = blockIdx.x;
    int tid = threadIdx.x;
    int warp = tid >> 5, lane = tid & 31;

    float4 a4 = *(const float4*)(A + (size_t)row * DMODEL + tid * 4);
    float4 r4 = *(const float4*)(R + (size_t)row * DMODEL + tid * 4);
    float x0 = a4.x + r4.x, x1 = a4.y + r4.y, x2 = a4.z + r4.z, x3 = a4.w + r4.w;

    float s = x0 + x1 + x2 + x3;
    s += __shfl_xor_sync(0xffffffffu, s, 16);
    s += __shfl_xor_sync(0xffffffffu, s, 8);
    s += __shfl_xor_sync(0xffffffffu, s, 4);
    s += __shfl_xor_sync(0xffffffffu, s, 2);
    s += __shfl_xor_sync(0xffffffffu, s, 1);
    if (lane == 0) red[warp] = s;
    __syncthreads();
    float mu = (red[0] + red[1] + red[2] + red[3]) * (1.0f / DMODEL);
    __syncthreads();

    float d0 = x0 - mu, d1 = x1 - mu, d2 = x2 - mu, d3 = x3 - mu;
    float s2 = d0*d0 + d1*d1 + d2*d2 + d3*d3;
    s2 += __shfl_xor_sync(0xffffffffu, s2, 16);
    s2 += __shfl_xor_sync(0xffffffffu, s2, 8);
    s2 += __shfl_xor_sync(0xffffffffu, s2, 4);
    s2 += __shfl_xor_sync(0xffffffffu, s2, 2);
    s2 += __shfl_xor_sync(0xffffffffu, s2, 1);
    if (lane == 0) red[warp] = s2;
    __syncthreads();
    float var = (red[0] + red[1] + red[2] + red[3]) * (1.0f / DMODEL);
    float rstd = rsqrtf(var + 1e-5f);

    float4 gv = *(const float4*)(g  + tid * 4);
    float4 bv = *(const float4*)(bb + tid * 4);
    float4 ov = make_float4(d0 * rstd * gv.x + bv.x,
                            d1 * rstd * gv.y + bv.y,
                            d2 * rstd * gv.z + bv.z,
                            d3 * rstd * gv.w + bv.w);
    *(float4*)(out + (size_t)row * DMODEL + tid * 4) = ov;
    uint32_t h0, l0, h1, l1;
    split2(ov.x, ov.y, h0, l0);
    split2(ov.z, ov.w, h1, l1);
    size_t pi = (size_t)row * 256 + tid * 2;
    *(uint2*)(Ohi + pi) = make_uint2(h0, h1);
    *(uint2*)(Olo + pi) = make_uint2(l0, l1);
}

// ---------------------------------------------------------------------------
// Head
// ---------------------------------------------------------------------------
__global__ void head_k(const float* __restrict__ H, const float* __restrict__ W,
                       const float* __restrict__ bh, float* __restrict__ out)
{
    int gw   = (blockIdx.x * blockDim.x + threadIdx.x) >> 5;
    int lane = threadIdx.x & 31;
    const float* r = H + (size_t)gw * DMODEL;
    float s = 0.0f;
#pragma unroll
    for (int k = 0; k < DMODEL / 32; k++)
        s = fmaf(r[lane + k * 32], W[lane + k * 32], s);
    s += __shfl_xor_sync(0xffffffffu, s, 16);
    s += __shfl_xor_sync(0xffffffffu, s, 8);
    s += __shfl_xor_sync(0xffffffffu, s, 4);
    s += __shfl_xor_sync(0xffffffffu, s, 2);
    s += __shfl_xor_sync(0xffffffffu, s, 1);
    if (lane == 0) out[gw] = s + bh[0];
}

// ---------------------------------------------------------------------------
// Launcher
// ---------------------------------------------------------------------------
extern "C" void kernel_launch(void* const* d_in, const int* in_sizes, int n_in,
                              void* d_out, int out_size)
{
    const int*   x     = (const int*)  d_in[0];
    const float* embed = (const float*)d_in[1];
    const float* pe    = (const float*)d_in[2];
    const float* Wqkv  = (const float*)d_in[3];
    const float* W0    = (const float*)d_in[4];
    const float* g1    = (const float*)d_in[5];
    const float* b1    = (const float*)d_in[6];
    const float* g2    = (const float*)d_in[7];
    const float* b2    = (const float*)d_in[8];
    const float* Wl1   = (const float*)d_in[9];
    const float* bl1   = (const float*)d_in[10];
    const float* Wl2   = (const float*)d_in[11];
    const float* bl2   = (const float*)d_in[12];
    const float* Wh    = (const float*)d_in[13];
    const float* bh    = (const float*)d_in[14];
    float* out = (float*)d_out;

    float *hb, *yb, *ab;
    uint32_t *hhi, *hlo, *yhi, *ylo, *aohi, *aolo, *midhi, *midlo;
    uint32_t *qhi, *qlo, *khi, *klo;
    __nv_bfloat16 *vhi, *vlo;
    uint32_t *wqh, *wql, *w0h, *w0l, *l1h, *l1l, *l2h, *l2l;
    cudaGetSymbolAddress((void**)&hb,    g_h);
    cudaGetSymbolAddress((void**)&yb,    g_y);
    cudaGetSymbolAddress((void**)&ab,    g_a);
    cudaGetSymbolAddress((void**)&hhi,   g_hhi);  cudaGetSymbolAddress((void**)&hlo,   g_hlo);
    cudaGetSymbolAddress((void**)&yhi,   g_yhi);  cudaGetSymbolAddress((void**)&ylo,   g_ylo);
    cudaGetSymbolAddress((void**)&aohi,  g_aohi); cudaGetSymbolAddress((void**)&aolo,  g_aolo);
    cudaGetSymbolAddress((void**)&midhi, g_midhi);cudaGetSymbolAddress((void**)&midlo, g_midlo);
    cudaGetSymbolAddress((void**)&qhi,   g_qhi);  cudaGetSymbolAddress((void**)&qlo,   g_qlo);
    cudaGetSymbolAddress((void**)&khi,   g_khi);  cudaGetSymbolAddress((void**)&klo,   g_klo);
    cudaGetSymbolAddress((void**)&vhi,   g_vhi);  cudaGetSymbolAddress((void**)&vlo,   g_vlo);
    cudaGetSymbolAddress((void**)&wqh,   g_wqkv_hi); cudaGetSymbolAddress((void**)&wql, g_wqkv_lo);
    cudaGetSymbolAddress((void**)&w0h,   g_w0_hi);   cudaGetSymbolAddress((void**)&w0l, g_w0_lo);
    cudaGetSymbolAddress((void**)&l1h,   g_l1_hi);   cudaGetSymbolAddress((void**)&l1l, g_l1_lo);
    cudaGetSymbolAddress((void**)&l2h,   g_l2_hi);   cudaGetSymbolAddress((void**)&l2l, g_l2_lo);

    cudaFuncSetAttribute(flash_mma, cudaFuncAttributeMaxDynamicSharedMemorySize, FLASH2_SMEM);
    cudaFuncSetAttribute(gemm_mma<0>, cudaFuncAttributeMaxDynamicSharedMemorySize, GMM_SMEM);
    cudaFuncSetAttribute(gemm_mma<1>, cudaFuncAttributeMaxDynamicSharedMemorySize, GMM_SMEM);
    cudaFuncSetAttribute(gemm_mma<2>, cudaFuncAttributeMaxDynamicSharedMemorySize, GMM_SMEM);
    cudaFuncSetAttribute(gemm_mma<3>, cudaFuncAttributeMaxDynamicSharedMemorySize, GMM_SMEM);

    // weight prep (once per launch)
    wqkvtrans_k<<<dim3((1536 * 256) / 256, NBLOCKS), 256>>>(Wqkv, wqh, wql);
    wtrans_k<<<dim3(16, 16, NBLOCKS), dim3(32, 8)>>>(W0,  w0h, w0l, DMODEL, DMODEL);
    wtrans_k<<<dim3(64, 16, NBLOCKS), dim3(32, 8)>>>(Wl1, l1h, l1l, DMODEL, DFF);
    wtrans_k<<<dim3(16, 64, NBLOCKS), dim3(32, 8)>>>(Wl2, l2h, l2l, DFF, DMODEL);

    embed_k<<<(NROWS * (DMODEL / 4)) / 256, 256>>>(x, embed, pe, hb, hhi, hlo);

    for (int i = 0; i < NBLOCKS; i++) {
        gemm_mma<3><<<dim3(12, 64), 256, GMM_SMEM>>>(
            hhi, hlo, wqh + (size_t)i * 1536 * 256, wql + (size_t)i * 1536 * 256,
            nullptr, nullptr, qhi, qlo, khi, klo, vhi, vlo,
            NROWS, 3 * DMODEL, DMODEL);

        flash_mma<<<dim3(SEQ / 128, NHEADS, BATCH), 256, FLASH2_SMEM>>>(
            qhi, qlo, khi, klo, vhi, vlo, aohi, aolo);

        gemm_mma<0><<<dim3(4, 64), 256, GMM_SMEM>>>(
            aohi, aolo, w0h + (size_t)i * 512 * 256, w0l + (size_t)i * 512 * 256,
            nullptr, ab, nullptr, nullptr, nullptr, nullptr, nullptr, nullptr,
            NROWS, DMODEL, DMODEL);

        add_ln_k<<<NROWS, 128>>>(ab, hb, g1 + i * DMODEL, b1 + i * DMODEL, yb, yhi, ylo);

        gemm_mma<2><<<dim3(16, 64), 256, GMM_SMEM>>>(
            yhi, ylo, l1h + (size_t)i * 2048 * 256, l1l + (size_t)i * 2048 * 256,
            bl1 + i * DFF, nullptr, midhi, midlo, nullptr, nullptr, nullptr, nullptr,
            NROWS, DFF, DMODEL);

        gemm_mma<1><<<dim3(4, 64), 256, GMM_SMEM>>>(
            midhi, midlo, l2h + (size_t)i * 512 * 1024, l2l + (size_t)i * 512 * 1024,
            bl2 + i * DMODEL, ab, nullptr, nullptr, nullptr, nullptr, nullptr, nullptr,
            NROWS, DMODEL, DFF);

        add_ln_k<<<NROWS, 128>>>(ab, yb, g2 + i * DMODEL, b2 + i * DMODEL, hb, hhi, hlo);
    }

    head_k<<<NROWS / 8, 256>>>(hb, Wh, bh, out);
}